// round 1
// baseline (speedup 1.0000x reference)
#include <cuda_runtime.h>

// 3-level db4 wavelet front-end, fully fused: one CTA per (b,c) row.
// Row length 8192; all intermediates in shared memory; 4 output bands
// written straight to gmem.

#define NT 512
#define LEN0 8192
#define LEN1 4100   // analysis out of 8192
#define LEN2 2054   // analysis out of 4100
#define LEN3 1031   // analysis out of 2054

// Analysis (decomposition) filters, applied as cross-correlation on
// reflect-padded input with stride 2 (matches lax.conv_general_dilated).
__constant__ float c_dec_lo[8] = {
    -0.0105974018f, 0.0328830117f, 0.0308413818f, -0.1870348117f,
    -0.0279837694f, 0.6308807679f, 0.7148465706f, 0.2303778133f};
__constant__ float c_dec_hi[8] = {
    -0.2303778133f, 0.7148465706f, -0.6308807679f, -0.0279837694f,
     0.1870348117f, 0.0308413818f, -0.0328830117f, -0.0105974018f};

// Synthesis (transpose conv, crop 7, T = 2L-8). Polyphase split:
//   out[2u]   = w[7]a[u]   + w[5]a[u+1] + w[3]a[u+2] + w[1]a[u+3]
//   out[2u+1] = w[6]a[u+1] + w[4]a[u+2] + w[2]a[u+3] + w[0]a[u+4]
// REC_LO even/odd tap sets:
__constant__ float c_lo_e[4] = {-0.0105974018f, 0.0308413818f, -0.0279837694f, 0.7148465706f};
__constant__ float c_lo_o[4] = { 0.0328830117f, -0.1870348117f, 0.6308807679f, 0.2303778133f};
// REC_HI even/odd tap sets:
__constant__ float c_hi_e[4] = {-0.2303778133f, -0.6308807679f, 0.1870348117f, -0.0328830117f};
__constant__ float c_hi_o[4] = { 0.7148465706f, -0.0279837694f, 0.0308413818f, -0.0105974018f};

// Analysis step: reflect pad 7 both sides, stride-2 correlation, both
// filters computed together (one smem read feeds 2 FMAs).
__device__ __forceinline__ void analysis_step(const float* __restrict__ in, int L,
                                              float* __restrict__ lo, float* __restrict__ hi,
                                              int Lout, int tid) {
    const int twoLm2 = 2 * L - 2;
    for (int o = tid; o < Lout; o += NT) {
        int base = 2 * o - 7;
        float sl = 0.f, sh = 0.f;
#pragma unroll
        for (int k = 0; k < 8; k++) {
            int i = base + k;
            i = i < 0 ? -i : i;            // left reflect
            i = min(i, twoLm2 - i);        // right reflect
            float v = in[i];
            sl = fmaf(v, c_dec_lo[k], sl);
            sh = fmaf(v, c_dec_hi[k], sh);
        }
        lo[o] = sl;
        hi[o] = sh;
    }
}

// Synthesis step into shared memory. Input length L, output length 2L-8.
__device__ __forceinline__ void synth_s(const float* __restrict__ a, int L,
                                        const float* __restrict__ wE, const float* __restrict__ wO,
                                        float* __restrict__ out, int tid) {
    const int halfT = L - 4;   // (2L-8)/2, always even lengths here
    const float e0 = wE[0], e1 = wE[1], e2 = wE[2], e3 = wE[3];
    const float o0 = wO[0], o1 = wO[1], o2 = wO[2], o3 = wO[3];
    for (int u = tid; u < halfT; u += NT) {
        float a0 = a[u], a1 = a[u + 1], a2 = a[u + 2], a3 = a[u + 3], a4 = a[u + 4];
        out[2 * u]     = fmaf(e0, a0, fmaf(e1, a1, fmaf(e2, a2, e3 * a3)));
        out[2 * u + 1] = fmaf(o0, a1, fmaf(o1, a2, fmaf(o2, a3, o3 * a4)));
    }
}

// Synthesis step straight to global memory (vectorized float2 store).
__device__ __forceinline__ void synth_g(const float* __restrict__ a, int L,
                                        const float* __restrict__ wE, const float* __restrict__ wO,
                                        float* __restrict__ outg, int tid) {
    const int halfT = L - 4;
    float2* o2p = reinterpret_cast<float2*>(outg);
    const float e0 = wE[0], e1 = wE[1], e2 = wE[2], e3 = wE[3];
    const float o0 = wO[0], o1 = wO[1], o2 = wO[2], o3 = wO[3];
    for (int u = tid; u < halfT; u += NT) {
        float a0 = a[u], a1 = a[u + 1], a2 = a[u + 2], a3 = a[u + 3], a4 = a[u + 4];
        float ev = fmaf(e0, a0, fmaf(e1, a1, fmaf(e2, a2, e3 * a3)));
        float od = fmaf(o0, a1, fmaf(o1, a2, fmaf(o2, a3, o3 * a4)));
        o2p[u] = make_float2(ev, od);
    }
}

__global__ void __launch_bounds__(NT, 2)
dwt_frontend_kernel(const float* __restrict__ x, float* __restrict__ out) {
    extern __shared__ float s[];
    float* X  = s;               // 8192
    float* D1 = X  + LEN0;       // 4100
    float* A1 = D1 + LEN1;       // 4100   (reused as recon scratch R4100)
    float* D2 = A1 + LEN1;       // 2054
    float* A2 = D2 + LEN2;       // 2054   (reused as recon scratch R2054)
    float* D3 = A2 + LEN2;       // 1031
    float* A3 = D3 + LEN3;       // 1031

    const int tid = threadIdx.x;
    const int row = blockIdx.x;
    const float* xg = x + (size_t)row * LEN0;

    // Load row into shared memory (float4 vectorized).
    {
        const float4* xg4 = reinterpret_cast<const float4*>(xg);
        float4* X4 = reinterpret_cast<float4*>(X);
        for (int i = tid; i < LEN0 / 4; i += NT) X4[i] = xg4[i];
    }
    __syncthreads();

    // Analysis cascade.
    analysis_step(X,  LEN0, A1, D1, LEN1, tid);
    __syncthreads();
    analysis_step(A1, LEN1, A2, D2, LEN2, tid);
    __syncthreads();
    analysis_step(A2, LEN2, A3, D3, LEN3, tid);
    __syncthreads();

    const size_t bstride = (size_t)gridDim.x * LEN0;
    float* ob = out + (size_t)row * LEN0;

    // Band 3: REC_HI(D1) -> 8192, straight to gmem.
    synth_g(D1, LEN1, c_hi_e, c_hi_o, ob + 3 * bstride, tid);
    // Band 2 stage 1: REC_HI(D2) -> 4100 into scratch A1.
    synth_s(D2, LEN2, c_hi_e, c_hi_o, A1, tid);
    __syncthreads();
    // Band 2 stage 2: REC_LO(A1) -> 8192 -> gmem.
    synth_g(A1, LEN1, c_lo_e, c_lo_o, ob + 2 * bstride, tid);
    // Band 1 stage 1: REC_HI(D3) -> 2054 into scratch A2.
    synth_s(D3, LEN3, c_hi_e, c_hi_o, A2, tid);
    __syncthreads();
    // Band 1 stage 2: REC_LO(A2) -> 4100 into A1.
    synth_s(A2, LEN2, c_lo_e, c_lo_o, A1, tid);
    __syncthreads();
    // Band 1 stage 3: REC_LO(A1) -> 8192 -> gmem.
    synth_g(A1, LEN1, c_lo_e, c_lo_o, ob + 1 * bstride, tid);
    // Band 0 stage 1: REC_LO(A3) -> 2054 into A2.
    synth_s(A3, LEN3, c_lo_e, c_lo_o, A2, tid);
    __syncthreads();
    // Band 0 stage 2: REC_LO(A2) -> 4100 into A1.
    synth_s(A2, LEN2, c_lo_e, c_lo_o, A1, tid);
    __syncthreads();
    // Band 0 stage 3: REC_LO(A1) -> 8192 -> gmem.
    synth_g(A1, LEN1, c_lo_e, c_lo_o, ob, tid);
}

extern "C" void kernel_launch(void* const* d_in, const int* in_sizes, int n_in,
                              void* d_out, int out_size) {
    const float* x = (const float*)d_in[0];
    float* out = (float*)d_out;
    const size_t smem = (size_t)(LEN0 + 2 * LEN1 + 2 * LEN2 + 2 * LEN3) * sizeof(float); // 90248 B
    cudaFuncSetAttribute(dwt_frontend_kernel,
                         cudaFuncAttributeMaxDynamicSharedMemorySize, (int)smem);
    // 16 * 128 = 2048 rows, one CTA each.
    dwt_frontend_kernel<<<2048, NT, smem>>>(x, out);
}